// round 3
// baseline (speedup 1.0000x reference)
#include <cuda_runtime.h>
#include <cstdint>

#define B_  16
#define S_  2048
#define D_  64
#define DV_ 512

// Dropout mask mode (JAX threefry variants).
//   3 = partitionable, bits = o0 ^ o1   (matches jax _threefry_random_bits_partitionable, bit_width=32)
//   0 = partitionable, bits = low word  (WRONG — that's the 64-bit path truncated; tried R1, rel_err 0.70)
//   1 = partitionable, bits = high word
//   2 = legacy pair scheme (non-partitionable)  <- next fallback if still 0.70
#define MASK_MODE 3

// ---------------- scratch (static device memory; no allocations) ------------
__device__ float g_K[S_ * D_];                          // K[j][d] = sum_c n[j,c]*m[d,c]
__device__ float g_P[(size_t)B_ * S_ * S_];             // 268 MB scores->probs

// ---------------- threefry2x32 (bit-exact vs JAX) ---------------------------
__device__ __forceinline__ unsigned int rotl32(unsigned int x, int r) {
    return __funnelshift_l(x, x, r);
}

__device__ __forceinline__ void threefry2x32(unsigned int k0, unsigned int k1,
                                             unsigned int& x0, unsigned int& x1) {
    unsigned int k2 = k0 ^ k1 ^ 0x1BD11BDAu;
    x0 += k0; x1 += k1;
#define TFR(r) { x0 += x1; x1 = rotl32(x1, (r)); x1 ^= x0; }
    TFR(13) TFR(15) TFR(26) TFR(6)
    x0 += k1; x1 += k2 + 1u;
    TFR(17) TFR(29) TFR(16) TFR(24)
    x0 += k2; x1 += k0 + 2u;
    TFR(13) TFR(15) TFR(26) TFR(6)
    x0 += k0; x1 += k1 + 3u;
    TFR(17) TFR(29) TFR(16) TFR(24)
    x0 += k1; x1 += k2 + 4u;
    TFR(13) TFR(15) TFR(26) TFR(6)
    x0 += k2; x1 += k0 + 5u;
#undef TFR
}

// keep iff uniform(bits) < 0.75  <=>  bits < 0xC0000000 (exact integer form)
__device__ __forceinline__ bool jax_keep(unsigned long long idx) {
#if MASK_MODE != 2
    unsigned int x0 = (unsigned int)(idx >> 32);
    unsigned int x1 = (unsigned int)idx;
    threefry2x32(0u, 42u, x0, x1);
#if MASK_MODE == 3
    unsigned int bits = x0 ^ x1;  // 32-bit partitionable path: o0 XOR o1
#elif MASK_MODE == 0
    unsigned int bits = x1;
#else
    unsigned int bits = x0;
#endif
#else
    const unsigned long long half = ((unsigned long long)B_ * S_ * S_) / 2ull;
    unsigned long long j = (idx < half) ? idx : (idx - half);
    unsigned int x0 = (unsigned int)j;
    unsigned int x1 = (unsigned int)(j + half);
    threefry2x32(0u, 42u, x0, x1);
    unsigned int bits = (idx < half) ? x0 : x1;
#endif
    return bits < 0xC0000000u;
}

// ---------------- kernel 1: K[j][d] = n[j,:] . m[d,:]  ----------------------
__global__ void k_build_K(const float* __restrict__ m, const float* __restrict__ n) {
    int j = blockIdx.x;      // 0..2047
    int d = threadIdx.x;     // 0..63
    const float4* n4 = reinterpret_cast<const float4*>(n + (size_t)j * 512);
    const float4* m4 = reinterpret_cast<const float4*>(m + (size_t)d * 512);
    float acc = 0.f;
#pragma unroll 8
    for (int c = 0; c < 128; ++c) {
        float4 a = __ldg(&n4[c]);
        float4 b = __ldg(&m4[c]);
        acc += a.x * b.x;
        acc += a.y * b.y;
        acc += a.z * b.z;
        acc += a.w * b.w;
    }
    g_K[j * D_ + d] = acc;
}

// ---------------- kernel 2: raw scores * (1/64) into g_P --------------------
// C[b][i][j] = (1/64) * sum_d x1[b][i][d] * K[j][d]
// grid (16 j-tiles, 16 i-tiles, 16 b), 256 threads, 128x128 tile, 8x8/thread.
__global__ void __launch_bounds__(256) k_scores(const float* __restrict__ x1) {
    const int bx = blockIdx.x;   // j tile
    const int by = blockIdx.y;   // i tile
    const int b  = blockIdx.z;

    const float* A  = x1 + ((size_t)b * S_ + (size_t)by * 128) * D_;  // 128 x 64
    const float* Kt = g_K + (size_t)bx * 128 * D_;                    // 128 x 64
    float* C = g_P + (size_t)b * S_ * S_ + (size_t)by * 128 * S_ + (size_t)bx * 128;

    __shared__ float As[32][132];   // [k][i]
    __shared__ float Bs[32][132];   // [k][j]

    const int tid = threadIdx.x;
    const int tx = tid & 15;        // 0..15 -> j sub
    const int ty = tid >> 4;        // 0..15 -> i sub

    float acc[8][8];
#pragma unroll
    for (int i = 0; i < 8; ++i)
#pragma unroll
        for (int j = 0; j < 8; ++j) acc[i][j] = 0.f;

    for (int kb = 0; kb < D_; kb += 32) {
        __syncthreads();
        // load A tile 128x32 (transposed into As[k][i])
#pragma unroll
        for (int l = 0; l < 4; ++l) {
            int f = tid + l * 256;           // 0..1023 float4 slots
            int row = f >> 3;                // 0..127
            int c4  = f & 7;                 // 0..7
            float4 v = *reinterpret_cast<const float4*>(A + (size_t)row * D_ + kb + c4 * 4);
            As[c4 * 4 + 0][row] = v.x;
            As[c4 * 4 + 1][row] = v.y;
            As[c4 * 4 + 2][row] = v.z;
            As[c4 * 4 + 3][row] = v.w;
        }
        // load K tile 128x32 (transposed into Bs[k][j])
#pragma unroll
        for (int l = 0; l < 4; ++l) {
            int f = tid + l * 256;
            int row = f >> 3;
            int c4  = f & 7;
            float4 v = *reinterpret_cast<const float4*>(Kt + (size_t)row * D_ + kb + c4 * 4);
            Bs[c4 * 4 + 0][row] = v.x;
            Bs[c4 * 4 + 1][row] = v.y;
            Bs[c4 * 4 + 2][row] = v.z;
            Bs[c4 * 4 + 3][row] = v.w;
        }
        __syncthreads();

#pragma unroll
        for (int k = 0; k < 32; ++k) {
            float ra[8], rb[8];
            *reinterpret_cast<float4*>(&ra[0]) = *reinterpret_cast<float4*>(&As[k][ty * 8]);
            *reinterpret_cast<float4*>(&ra[4]) = *reinterpret_cast<float4*>(&As[k][ty * 8 + 4]);
            *reinterpret_cast<float4*>(&rb[0]) = *reinterpret_cast<float4*>(&Bs[k][tx * 8]);
            *reinterpret_cast<float4*>(&rb[4]) = *reinterpret_cast<float4*>(&Bs[k][tx * 8 + 4]);
#pragma unroll
            for (int i = 0; i < 8; ++i)
#pragma unroll
                for (int j = 0; j < 8; ++j)
                    acc[i][j] += ra[i] * rb[j];
        }
    }

    const float scale = 0.015625f;  // 1/64, exact
#pragma unroll
    for (int i = 0; i < 8; ++i) {
        float* crow = C + (size_t)(ty * 8 + i) * S_ + tx * 8;
        float4 v0 = make_float4(acc[i][0] * scale, acc[i][1] * scale,
                                acc[i][2] * scale, acc[i][3] * scale);
        float4 v1 = make_float4(acc[i][4] * scale, acc[i][5] * scale,
                                acc[i][6] * scale, acc[i][7] * scale);
        *reinterpret_cast<float4*>(crow)     = v0;
        *reinterpret_cast<float4*>(crow + 4) = v1;
    }
}

// ---------------- kernel 3: row softmax + threefry dropout in-place ---------
__global__ void __launch_bounds__(256) k_softmax_drop() {
    const size_t row = blockIdx.x;                 // b*2048 + i, 0..32767
    float* p = g_P + row * (size_t)S_;
    const int tid  = threadIdx.x;
    const int lane = tid & 31;
    const int w    = tid >> 5;

    float v[8];
#pragma unroll
    for (int k = 0; k < 8; ++k) v[k] = p[tid + 256 * k];

    float mx = v[0];
#pragma unroll
    for (int k = 1; k < 8; ++k) mx = fmaxf(mx, v[k]);
#pragma unroll
    for (int o = 16; o > 0; o >>= 1) mx = fmaxf(mx, __shfl_xor_sync(0xffffffffu, mx, o));

    __shared__ float redmax[8];
    __shared__ float redsum[8];
    if (lane == 0) redmax[w] = mx;
    __syncthreads();
    float M = redmax[0];
#pragma unroll
    for (int i = 1; i < 8; ++i) M = fmaxf(M, redmax[i]);

    float e[8];
    float s = 0.f;
#pragma unroll
    for (int k = 0; k < 8; ++k) { e[k] = __expf(v[k] - M); s += e[k]; }
#pragma unroll
    for (int o = 16; o > 0; o >>= 1) s += __shfl_xor_sync(0xffffffffu, s, o);
    if (lane == 0) redsum[w] = s;
    __syncthreads();
    float Z = redsum[0];
#pragma unroll
    for (int i = 1; i < 8; ++i) Z += redsum[i];

    const float invZ = 1.0f / Z;
    const float inv_keep = 1.0f / 0.75f;
    const size_t base = row * (size_t)S_;
#pragma unroll
    for (int k = 0; k < 8; ++k) {
        size_t idx = base + (size_t)(tid + 256 * k);
        bool keep = jax_keep((unsigned long long)idx);
        p[tid + 256 * k] = keep ? e[k] * invZ * inv_keep : 0.0f;
    }
}

// ---------------- kernel 4: out[b] = P[b] @ q  (2048x2048 @ 2048x512) -------
// grid (4 dv-tiles, 16 i-tiles, 16 b), 256 threads, 128x128 tile, BK=16,
// double-buffered smem, 8x8 register tile per thread.
__global__ void __launch_bounds__(256) k_pv(const float* __restrict__ q,
                                            float* __restrict__ out) {
    const int bn = blockIdx.x;   // dv tile (0..3)
    const int bm = blockIdx.y;   // i tile  (0..15)
    const int b  = blockIdx.z;

    const float* A  = g_P + (size_t)b * S_ * S_ + (size_t)bm * 128 * S_;
    const float* Bq = q + (size_t)bn * 128;
    float* C = out + (size_t)b * S_ * DV_ + (size_t)bm * 128 * DV_ + (size_t)bn * 128;

    __shared__ float As[2][16][132];   // [buf][k][m]
    __shared__ float Bs[2][16][128];   // [buf][k][n]

    const int tid = threadIdx.x;
    const int tx = tid & 15;
    const int ty = tid >> 4;

    float acc[8][8];
#pragma unroll
    for (int i = 0; i < 8; ++i)
#pragma unroll
        for (int j = 0; j < 8; ++j) acc[i][j] = 0.f;

    auto loadA = [&](int kt, int bufi) {
#pragma unroll
        for (int l = 0; l < 2; ++l) {
            int f = tid + l * 256;            // 0..511 float4 slots (128 rows x 4)
            int row = f >> 2;                 // 0..127
            int c4  = (f & 3) * 4;            // 0,4,8,12
            float4 v = *reinterpret_cast<const float4*>(A + (size_t)row * S_ + kt + c4);
            As[bufi][c4 + 0][row] = v.x;
            As[bufi][c4 + 1][row] = v.y;
            As[bufi][c4 + 2][row] = v.z;
            As[bufi][c4 + 3][row] = v.w;
        }
    };
    auto loadB = [&](int kt, int bufi) {
#pragma unroll
        for (int l = 0; l < 2; ++l) {
            int f = tid + l * 256;            // 0..511 float4 slots (16 rows x 32)
            int row = f >> 5;                 // 0..15
            int c4  = (f & 31) * 4;           // 0..124
            float4 v = *reinterpret_cast<const float4*>(Bq + (size_t)(kt + row) * DV_ + c4);
            *reinterpret_cast<float4*>(&Bs[bufi][row][c4]) = v;
        }
    };

    loadA(0, 0);
    loadB(0, 0);
    __syncthreads();

    int buf = 0;
    for (int kt = 0; kt < S_; kt += 16) {
        if (kt + 16 < S_) {
            loadA(kt + 16, buf ^ 1);
            loadB(kt + 16, buf ^ 1);
        }
#pragma unroll
        for (int k = 0; k < 16; ++k) {
            float ra[8], rb[8];
            *reinterpret_cast<float4*>(&ra[0]) = *reinterpret_cast<float4*>(&As[buf][k][ty * 8]);
            *reinterpret_cast<float4*>(&ra[4]) = *reinterpret_cast<float4*>(&As[buf][k][ty * 8 + 4]);
            *reinterpret_cast<float4*>(&rb[0]) = *reinterpret_cast<float4*>(&Bs[buf][k][tx * 8]);
            *reinterpret_cast<float4*>(&rb[4]) = *reinterpret_cast<float4*>(&Bs[buf][k][tx * 8 + 4]);
#pragma unroll
            for (int i = 0; i < 8; ++i)
#pragma unroll
                for (int j = 0; j < 8; ++j)
                    acc[i][j] += ra[i] * rb[j];
        }
        __syncthreads();
        buf ^= 1;
    }

#pragma unroll
    for (int i = 0; i < 8; ++i) {
        float* crow = C + (size_t)(ty * 8 + i) * DV_ + tx * 8;
        *reinterpret_cast<float4*>(crow) =
            make_float4(acc[i][0], acc[i][1], acc[i][2], acc[i][3]);
        *reinterpret_cast<float4*>(crow + 4) =
            make_float4(acc[i][4], acc[i][5], acc[i][6], acc[i][7]);
    }
}

// ---------------- launch -----------------------------------------------------
extern "C" void kernel_launch(void* const* d_in, const int* in_sizes, int n_in,
                              void* d_out, int out_size) {
    const float* x1 = (const float*)d_in[0];   // [16,2048,64]
    const float* m  = (const float*)d_in[1];   // [64,512]
    const float* n  = (const float*)d_in[2];   // [2048,512]
    const float* q  = (const float*)d_in[3];   // [2048,512]
    float* out = (float*)d_out;                // [16,2048,512]

    k_build_K<<<S_, D_>>>(m, n);

    dim3 g2(S_ / 128, S_ / 128, B_);
    k_scores<<<g2, 256>>>(x1);

    k_softmax_drop<<<B_ * S_, 256>>>();

    dim3 g4(DV_ / 128, S_ / 128, B_);
    k_pv<<<g4, 256>>>(q, out);
}

// round 8
// speedup vs baseline: 1.9664x; 1.9664x over previous
#include <cuda_runtime.h>
#include <cstdint>

#define B_  16
#define S_  2048
#define D_  64
#define DV_ 512

// ---------------- scratch (static device memory; no allocations) ------------
__device__ float g_K[S_ * D_];                          // K[j][d]
__device__ float g_P[(size_t)B_ * S_ * S_];             // 268 MB scores->probs
__device__ float g_qT[(size_t)DV_ * S_];                // q transposed [512][2048]

// ---------------- threefry2x32 (bit-exact vs JAX, verified R3) ---------------
__device__ __forceinline__ unsigned int rotl32(unsigned int x, int r) {
    return __funnelshift_l(x, x, r);
}

__device__ __forceinline__ void threefry2x32(unsigned int k0, unsigned int k1,
                                             unsigned int& x0, unsigned int& x1) {
    unsigned int k2 = k0 ^ k1 ^ 0x1BD11BDAu;
    x0 += k0; x1 += k1;
#define TFR(r) { x0 += x1; x1 = rotl32(x1, (r)); x1 ^= x0; }
    TFR(13) TFR(15) TFR(26) TFR(6)
    x0 += k1; x1 += k2 + 1u;
    TFR(17) TFR(29) TFR(16) TFR(24)
    x0 += k2; x1 += k0 + 2u;
    TFR(13) TFR(15) TFR(26) TFR(6)
    x0 += k0; x1 += k1 + 3u;
    TFR(17) TFR(29) TFR(16) TFR(24)
    x0 += k1; x1 += k2 + 4u;
    TFR(13) TFR(15) TFR(26) TFR(6)
    x0 += k2; x1 += k0 + 5u;
#undef TFR
}

__device__ __forceinline__ bool jax_keep(unsigned long long idx) {
    unsigned int x0 = (unsigned int)(idx >> 32);
    unsigned int x1 = (unsigned int)idx;
    threefry2x32(0u, 42u, x0, x1);
    unsigned int bits = x0 ^ x1;      // 32-bit partitionable path
    return bits < 0xC0000000u;        // u < 0.75 exactly
}

// ---------------- helpers ----------------------------------------------------
__device__ __forceinline__ uint32_t f2tf32(float x) {      // RN round to tf32
    uint32_t u;
    asm("cvt.rna.tf32.f32 %0, %1;" : "=r"(u) : "f"(x));
    return u;
}

__device__ __forceinline__ void mma_16x8x8_tf32(float* c, const uint32_t* a,
                                                uint32_t b0, uint32_t b1) {
    asm volatile(
        "mma.sync.aligned.m16n8k8.row.col.f32.tf32.tf32.f32 "
        "{%0,%1,%2,%3}, {%4,%5,%6,%7}, {%8,%9}, {%0,%1,%2,%3};"
        : "+f"(c[0]), "+f"(c[1]), "+f"(c[2]), "+f"(c[3])
        : "r"(a[0]), "r"(a[1]), "r"(a[2]), "r"(a[3]), "r"(b0), "r"(b1));
}

// ---------------- kernel 1: K[j][d] = n[j,:] . m[d,:]  ----------------------
__global__ void k_build_K(const float* __restrict__ m, const float* __restrict__ n) {
    int j = blockIdx.x;
    int d = threadIdx.x;
    const float4* n4 = reinterpret_cast<const float4*>(n + (size_t)j * 512);
    const float4* m4 = reinterpret_cast<const float4*>(m + (size_t)d * 512);
    float acc = 0.f;
#pragma unroll 8
    for (int c = 0; c < 128; ++c) {
        float4 a = __ldg(&n4[c]);
        float4 b = __ldg(&m4[c]);
        acc += a.x * b.x;
        acc += a.y * b.y;
        acc += a.z * b.z;
        acc += a.w * b.w;
    }
    g_K[j * D_ + d] = acc;
}

// ---------------- kernel 1b: q transpose -> g_qT[n][k] ----------------------
__global__ void k_qT(const float* __restrict__ q) {
    __shared__ float tile[32][33];
    int n0 = blockIdx.x * 32;   // over DV
    int k0 = blockIdx.y * 32;   // over S
    int tx = threadIdx.x, ty = threadIdx.y;
#pragma unroll
    for (int j = 0; j < 32; j += 8)
        tile[ty + j][tx] = q[(size_t)(k0 + ty + j) * DV_ + n0 + tx];
    __syncthreads();
#pragma unroll
    for (int j = 0; j < 32; j += 8)
        g_qT[(size_t)(n0 + ty + j) * S_ + k0 + tx] = tile[tx][ty + j];
}

// ---------------- kernel 2: raw scores * (1/64) into g_P --------------------
__global__ void __launch_bounds__(256) k_scores(const float* __restrict__ x1) {
    const int bx = blockIdx.x;
    const int by = blockIdx.y;
    const int b  = blockIdx.z;

    const float* A  = x1 + ((size_t)b * S_ + (size_t)by * 128) * D_;
    const float* Kt = g_K + (size_t)bx * 128 * D_;
    float* C = g_P + (size_t)b * S_ * S_ + (size_t)by * 128 * S_ + (size_t)bx * 128;

    __shared__ float As[32][132];
    __shared__ float Bs[32][132];

    const int tid = threadIdx.x;
    const int tx = tid & 15;
    const int ty = tid >> 4;

    float acc[8][8];
#pragma unroll
    for (int i = 0; i < 8; ++i)
#pragma unroll
        for (int j = 0; j < 8; ++j) acc[i][j] = 0.f;

    for (int kb = 0; kb < D_; kb += 32) {
        __syncthreads();
#pragma unroll
        for (int l = 0; l < 4; ++l) {
            int f = tid + l * 256;
            int row = f >> 3;
            int c4  = f & 7;
            float4 v = *reinterpret_cast<const float4*>(A + (size_t)row * D_ + kb + c4 * 4);
            As[c4 * 4 + 0][row] = v.x;
            As[c4 * 4 + 1][row] = v.y;
            As[c4 * 4 + 2][row] = v.z;
            As[c4 * 4 + 3][row] = v.w;
        }
#pragma unroll
        for (int l = 0; l < 4; ++l) {
            int f = tid + l * 256;
            int row = f >> 3;
            int c4  = f & 7;
            float4 v = *reinterpret_cast<const float4*>(Kt + (size_t)row * D_ + kb + c4 * 4);
            Bs[c4 * 4 + 0][row] = v.x;
            Bs[c4 * 4 + 1][row] = v.y;
            Bs[c4 * 4 + 2][row] = v.z;
            Bs[c4 * 4 + 3][row] = v.w;
        }
        __syncthreads();

#pragma unroll
        for (int k = 0; k < 32; ++k) {
            float ra[8], rb[8];
            *reinterpret_cast<float4*>(&ra[0]) = *reinterpret_cast<float4*>(&As[k][ty * 8]);
            *reinterpret_cast<float4*>(&ra[4]) = *reinterpret_cast<float4*>(&As[k][ty * 8 + 4]);
            *reinterpret_cast<float4*>(&rb[0]) = *reinterpret_cast<float4*>(&Bs[k][tx * 8]);
            *reinterpret_cast<float4*>(&rb[4]) = *reinterpret_cast<float4*>(&Bs[k][tx * 8 + 4]);
#pragma unroll
            for (int i = 0; i < 8; ++i)
#pragma unroll
                for (int j = 0; j < 8; ++j)
                    acc[i][j] += ra[i] * rb[j];
        }
    }

    const float scale = 0.015625f;
#pragma unroll
    for (int i = 0; i < 8; ++i) {
        float* crow = C + (size_t)(ty * 8 + i) * S_ + tx * 8;
        *reinterpret_cast<float4*>(crow) = make_float4(acc[i][0] * scale, acc[i][1] * scale,
                                                       acc[i][2] * scale, acc[i][3] * scale);
        *reinterpret_cast<float4*>(crow + 4) = make_float4(acc[i][4] * scale, acc[i][5] * scale,
                                                           acc[i][6] * scale, acc[i][7] * scale);
    }
}

// ---------------- kernel 3: row softmax + threefry dropout in-place ---------
__global__ void __launch_bounds__(256) k_softmax_drop() {
    const size_t row = blockIdx.x;
    float* p = g_P + row * (size_t)S_;
    const int tid  = threadIdx.x;
    const int lane = tid & 31;
    const int w    = tid >> 5;

    float v[8];
#pragma unroll
    for (int k = 0; k < 8; ++k) v[k] = p[tid + 256 * k];

    float mx = v[0];
#pragma unroll
    for (int k = 1; k < 8; ++k) mx = fmaxf(mx, v[k]);
#pragma unroll
    for (int o = 16; o > 0; o >>= 1) mx = fmaxf(mx, __shfl_xor_sync(0xffffffffu, mx, o));

    __shared__ float redmax[8];
    __shared__ float redsum[8];
    if (lane == 0) redmax[w] = mx;
    __syncthreads();
    float M = redmax[0];
#pragma unroll
    for (int i = 1; i < 8; ++i) M = fmaxf(M, redmax[i]);

    float e[8];
    float s = 0.f;
#pragma unroll
    for (int k = 0; k < 8; ++k) { e[k] = __expf(v[k] - M); s += e[k]; }
#pragma unroll
    for (int o = 16; o > 0; o >>= 1) s += __shfl_xor_sync(0xffffffffu, s, o);
    if (lane == 0) redsum[w] = s;
    __syncthreads();
    float Z = redsum[0];
#pragma unroll
    for (int i = 1; i < 8; ++i) Z += redsum[i];

    const float invZ = 1.0f / Z;
    const float inv_keep = 1.0f / 0.75f;
    const size_t base = row * (size_t)S_;
#pragma unroll
    for (int k = 0; k < 8; ++k) {
        size_t idx = base + (size_t)(tid + 256 * k);
        bool keep = jax_keep((unsigned long long)idx);
        p[tid + 256 * k] = keep ? e[k] * invZ * inv_keep : 0.0f;
    }
}

// ---------------- kernel 4: PV via mma.sync tf32 -----------------------------
// out[b] tile [128 x 128] = P[128 x 2048] @ q[2048 x 128-slice]
// 256 threads = 8 warps (4m x 2n), warp tile 32m x 64n, m16n8k8 atoms, BK=32,
// double-buffered smem with 36-float row stride (conflict-free fragment LDS).
#define PV_STRIDE 36
#define PV_BUF_FLOATS (128 * PV_STRIDE)                 // 4608 floats per tile buffer
#define PV_SMEM_TOTAL (4 * PV_BUF_FLOATS * 4)           // A0,A1,B0,B1 = 73728 B

__global__ void __launch_bounds__(256, 2) k_pv_mma(float* __restrict__ out) {
    extern __shared__ uint32_t sm[];
    // layout: A buffers [0..2*4608), B buffers [2*4608..4*4608)
    const int tid = threadIdx.x;
    const int wid = tid >> 5;
    const int lane = tid & 31;
    const int g = lane >> 2;        // groupID 0..7
    const int t = lane & 3;         // thread-in-group 0..3
    const int wm = wid >> 1;        // 0..3  (m quadrant, 32 rows)
    const int wn = wid & 1;         // 0..1  (n half, 64 cols)
    const int bn = blockIdx.x, bm = blockIdx.y, b = blockIdx.z;

    const float* Ag = g_P + (size_t)b * S_ * S_ + (size_t)bm * 128 * S_;   // P rows
    const float* Bg = g_qT + (size_t)bn * 128 * S_;                        // qT rows

    float acc[2][8][4];
#pragma unroll
    for (int i = 0; i < 2; ++i)
#pragma unroll
        for (int j = 0; j < 8; ++j)
#pragma unroll
            for (int k = 0; k < 4; ++k) acc[i][j][k] = 0.f;

    auto stage = [&](int chunk, int buf) {
        const int k0 = chunk * 32;
        uint32_t* Asb = sm + buf * PV_BUF_FLOATS;
        uint32_t* Bsb = sm + 2 * PV_BUF_FLOATS + buf * PV_BUF_FLOATS;
#pragma unroll
        for (int l = 0; l < 4; ++l) {
            int slot = tid + l * 256;       // 0..1023
            int row  = slot >> 3;           // 0..127
            int c4   = (slot & 7) * 4;      // 0..28
            float4 va = *reinterpret_cast<const float4*>(Ag + (size_t)row * S_ + k0 + c4);
            *reinterpret_cast<uint4*>(&Asb[row * PV_STRIDE + c4]) =
                make_uint4(f2tf32(va.x), f2tf32(va.y), f2tf32(va.z), f2tf32(va.w));
            float4 vb = *reinterpret_cast<const float4*>(Bg + (size_t)row * S_ + k0 + c4);
            *reinterpret_cast<uint4*>(&Bsb[row * PV_STRIDE + c4]) =
                make_uint4(f2tf32(vb.x), f2tf32(vb.y), f2tf32(vb.z), f2tf32(vb.w));
        }
    };

    stage(0, 0);
    __syncthreads();

    for (int ch = 0; ch < S_ / 32; ++ch) {
        const int buf = ch & 1;
        if (ch + 1 < S_ / 32) stage(ch + 1, buf ^ 1);

        const uint32_t* Asb = sm + buf * PV_BUF_FLOATS;
        const uint32_t* Bsb = sm + 2 * PV_BUF_FLOATS + buf * PV_BUF_FLOATS;

#pragma unroll
        for (int ks = 0; ks < 4; ++ks) {
            const int kk = ks * 8;
            uint32_t af[2][4];
#pragma unroll
            for (int ma = 0; ma < 2; ++ma) {
                int r0 = wm * 32 + ma * 16 + g;
                af[ma][0] = Asb[r0 * PV_STRIDE + kk + t];
                af[ma][1] = Asb[(r0 + 8) * PV_STRIDE + kk + t];
                af[ma][2] = Asb[r0 * PV_STRIDE + kk + t + 4];
                af[ma][3] = Asb[(r0 + 8) * PV_STRIDE + kk + t + 4];
            }
#pragma unroll
            for (int nb = 0; nb < 8; ++nb) {
                int n0 = wn * 64 + nb * 8 + g;
                uint32_t b0 = Bsb[n0 * PV_STRIDE + kk + t];
                uint32_t b1 = Bsb[n0 * PV_STRIDE + kk + t + 4];
                mma_16x8x8_tf32(acc[0][nb], af[0], b0, b1);
                mma_16x8x8_tf32(acc[1][nb], af[1], b0, b1);
            }
        }
        __syncthreads();
    }

    // epilogue: c0,c1 -> row g, cols 2t,2t+1 ; c2,c3 -> row g+8
#pragma unroll
    for (int ma = 0; ma < 2; ++ma) {
        int row0 = bm * 128 + wm * 32 + ma * 16 + g;
#pragma unroll
        for (int nb = 0; nb < 8; ++nb) {
            int col = bn * 128 + wn * 64 + nb * 8 + 2 * t;
            float* p0 = out + ((size_t)b * S_ + row0) * DV_ + col;
            float* p1 = out + ((size_t)b * S_ + row0 + 8) * DV_ + col;
            *reinterpret_cast<float2*>(p0) = make_float2(acc[ma][nb][0], acc[ma][nb][1]);
            *reinterpret_cast<float2*>(p1) = make_float2(acc[ma][nb][2], acc[ma][nb][3]);
        }
    }
}

// ---------------- launch -----------------------------------------------------
extern "C" void kernel_launch(void* const* d_in, const int* in_sizes, int n_in,
                              void* d_out, int out_size) {
    const float* x1 = (const float*)d_in[0];   // [16,2048,64]
    const float* m  = (const float*)d_in[1];   // [64,512]
    const float* n  = (const float*)d_in[2];   // [2048,512]
    const float* q  = (const float*)d_in[3];   // [2048,512]
    float* out = (float*)d_out;                // [16,2048,512]

    cudaFuncSetAttribute(k_pv_mma, cudaFuncAttributeMaxDynamicSharedMemorySize,
                         PV_SMEM_TOTAL);

    k_build_K<<<S_, D_>>>(m, n);

    dim3 gt(DV_ / 32, S_ / 32);
    k_qT<<<gt, dim3(32, 8)>>>(q);

    dim3 g2(S_ / 128, S_ / 128, B_);
    k_scores<<<g2, 256>>>(x1);

    k_softmax_drop<<<B_ * S_, 256>>>();

    dim3 g4(DV_ / 128, S_ / 128, B_);
    k_pv_mma<<<g4, 256, PV_SMEM_TOTAL>>>(out);
}

// round 9
// speedup vs baseline: 2.6446x; 1.3449x over previous
#include <cuda_runtime.h>
#include <cuda_fp16.h>
#include <cstdint>

#define B_  16
#define S_  2048
#define D_  64
#define DV_ 512

// ---------------- scratch (static device memory; no allocations) ------------
__device__ float  g_K[S_ * D_];                          // K[j][d] fp32
__device__ float  g_P[(size_t)B_ * S_ * S_];             // 268 MB raw scores (fp32)
__device__ __half g_Ph[(size_t)B_ * S_ * S_];            // 134 MB probs (fp16)
__device__ __half g_qTh[(size_t)DV_ * S_];               // q transposed fp16 [512][2048]

// ---------------- threefry2x32 (bit-exact vs JAX, verified R3) ---------------
__device__ __forceinline__ unsigned int rotl32(unsigned int x, int r) {
    return __funnelshift_l(x, x, r);
}

__device__ __forceinline__ void threefry2x32(unsigned int k0, unsigned int k1,
                                             unsigned int& x0, unsigned int& x1) {
    unsigned int k2 = k0 ^ k1 ^ 0x1BD11BDAu;
    x0 += k0; x1 += k1;
#define TFR(r) { x0 += x1; x1 = rotl32(x1, (r)); x1 ^= x0; }
    TFR(13) TFR(15) TFR(26) TFR(6)
    x0 += k1; x1 += k2 + 1u;
    TFR(17) TFR(29) TFR(16) TFR(24)
    x0 += k2; x1 += k0 + 2u;
    TFR(13) TFR(15) TFR(26) TFR(6)
    x0 += k0; x1 += k1 + 3u;
    TFR(17) TFR(29) TFR(16) TFR(24)
    x0 += k1; x1 += k2 + 4u;
    TFR(13) TFR(15) TFR(26) TFR(6)
    x0 += k2; x1 += k0 + 5u;
#undef TFR
}

__device__ __forceinline__ bool jax_keep(unsigned long long idx) {
    unsigned int x0 = (unsigned int)(idx >> 32);
    unsigned int x1 = (unsigned int)idx;
    threefry2x32(0u, 42u, x0, x1);
    return (x0 ^ x1) < 0xC0000000u;   // u < 0.75 exactly
}

// ---------------- helpers ----------------------------------------------------
__device__ __forceinline__ uint32_t f2tf32(float x) {
    uint32_t u;
    asm("cvt.rna.tf32.f32 %0, %1;" : "=r"(u) : "f"(x));
    return u;
}

__device__ __forceinline__ void mma_tf32(float* c, const uint32_t* a,
                                         uint32_t b0, uint32_t b1) {
    asm volatile(
        "mma.sync.aligned.m16n8k8.row.col.f32.tf32.tf32.f32 "
        "{%0,%1,%2,%3}, {%4,%5,%6,%7}, {%8,%9}, {%0,%1,%2,%3};"
        : "+f"(c[0]), "+f"(c[1]), "+f"(c[2]), "+f"(c[3])
        : "r"(a[0]), "r"(a[1]), "r"(a[2]), "r"(a[3]), "r"(b0), "r"(b1));
}

__device__ __forceinline__ void mma_f16(float* c, const uint32_t* a,
                                        uint32_t b0, uint32_t b1) {
    asm volatile(
        "mma.sync.aligned.m16n8k16.row.col.f32.f16.f16.f32 "
        "{%0,%1,%2,%3}, {%4,%5,%6,%7}, {%8,%9}, {%0,%1,%2,%3};"
        : "+f"(c[0]), "+f"(c[1]), "+f"(c[2]), "+f"(c[3])
        : "r"(a[0]), "r"(a[1]), "r"(a[2]), "r"(a[3]), "r"(b0), "r"(b1));
}

// ---------------- kernel 1: K[j][d] = n[j,:] . m[d,:]  ----------------------
__global__ void k_build_K(const float* __restrict__ m, const float* __restrict__ n) {
    int j = blockIdx.x;
    int d = threadIdx.x;
    const float4* n4 = reinterpret_cast<const float4*>(n + (size_t)j * 512);
    const float4* m4 = reinterpret_cast<const float4*>(m + (size_t)d * 512);
    float acc = 0.f;
#pragma unroll 8
    for (int c = 0; c < 128; ++c) {
        float4 a = __ldg(&n4[c]);
        float4 b = __ldg(&m4[c]);
        acc += a.x * b.x;
        acc += a.y * b.y;
        acc += a.z * b.z;
        acc += a.w * b.w;
    }
    g_K[j * D_ + d] = acc;
}

// ---------------- kernel 1b: q transpose -> g_qTh[n][k] (fp16) --------------
__global__ void k_qT(const float* __restrict__ q) {
    __shared__ float tile[32][33];
    int n0 = blockIdx.x * 32;   // over DV
    int k0 = blockIdx.y * 32;   // over S
    int tx = threadIdx.x, ty = threadIdx.y;
#pragma unroll
    for (int j = 0; j < 32; j += 8)
        tile[ty + j][tx] = q[(size_t)(k0 + ty + j) * DV_ + n0 + tx];
    __syncthreads();
#pragma unroll
    for (int j = 0; j < 32; j += 8)
        g_qTh[(size_t)(n0 + ty + j) * S_ + k0 + tx] = __float2half_rn(tile[tx][ty + j]);
}

// ---------------- kernel 2: scores via split-tf32 mma.sync -------------------
// C[b][i][j] (128x128 tile) = (1/64) * x1strip[128x64] @ K[jtile 128x64]^T
// split-tf32: acc = hi*hi + hi*lo + lo*hi  (~fp32 accuracy)
#define SC_STRIDE 68
#define SC_PLANE (128 * SC_STRIDE)
#define SC_SMEM_TOTAL (4 * SC_PLANE * 4)   // Ahi,Alo,Bhi,Blo = 139264 B

__global__ void __launch_bounds__(256) k_scores_mma(const float* __restrict__ x1) {
    extern __shared__ uint32_t sm[];
    uint32_t* Ahi = sm;
    uint32_t* Alo = sm + SC_PLANE;
    uint32_t* Bhi = sm + 2 * SC_PLANE;
    uint32_t* Blo = sm + 3 * SC_PLANE;

    const int tid = threadIdx.x;
    const int wid = tid >> 5;
    const int lane = tid & 31;
    const int g = lane >> 2, t = lane & 3;
    const int wm = wid >> 1, wn = wid & 1;
    const int bx = blockIdx.x;   // j tile
    const int bm = blockIdx.y;   // i tile
    const int b  = blockIdx.z;

    const float* Ax = x1 + ((size_t)b * S_ + (size_t)bm * 128) * D_;
    const float* Kx = g_K + (size_t)bx * 128 * D_;

    // stage A and B tiles as hi/lo tf32 planes
#pragma unroll
    for (int l = 0; l < 8; ++l) {
        int slot = tid + l * 256;        // 0..2047
        int row = slot >> 4;             // 0..127
        int c4  = (slot & 15) * 4;       // 0..60
        float4 va = *reinterpret_cast<const float4*>(Ax + (size_t)row * D_ + c4);
        uint32_t h0 = f2tf32(va.x), h1 = f2tf32(va.y), h2 = f2tf32(va.z), h3 = f2tf32(va.w);
        uint32_t l0 = f2tf32(va.x - __uint_as_float(h0));
        uint32_t l1 = f2tf32(va.y - __uint_as_float(h1));
        uint32_t l2 = f2tf32(va.z - __uint_as_float(h2));
        uint32_t l3 = f2tf32(va.w - __uint_as_float(h3));
        *reinterpret_cast<uint4*>(&Ahi[row * SC_STRIDE + c4]) = make_uint4(h0, h1, h2, h3);
        *reinterpret_cast<uint4*>(&Alo[row * SC_STRIDE + c4]) = make_uint4(l0, l1, l2, l3);

        float4 vb = *reinterpret_cast<const float4*>(Kx + (size_t)row * D_ + c4);
        uint32_t p0 = f2tf32(vb.x), p1 = f2tf32(vb.y), p2 = f2tf32(vb.z), p3 = f2tf32(vb.w);
        uint32_t q0 = f2tf32(vb.x - __uint_as_float(p0));
        uint32_t q1 = f2tf32(vb.y - __uint_as_float(p1));
        uint32_t q2 = f2tf32(vb.z - __uint_as_float(p2));
        uint32_t q3 = f2tf32(vb.w - __uint_as_float(p3));
        *reinterpret_cast<uint4*>(&Bhi[row * SC_STRIDE + c4]) = make_uint4(p0, p1, p2, p3);
        *reinterpret_cast<uint4*>(&Blo[row * SC_STRIDE + c4]) = make_uint4(q0, q1, q2, q3);
    }
    __syncthreads();

    float acc[2][8][4];
#pragma unroll
    for (int i = 0; i < 2; ++i)
#pragma unroll
        for (int j = 0; j < 8; ++j)
#pragma unroll
            for (int k = 0; k < 4; ++k) acc[i][j][k] = 0.f;

#pragma unroll
    for (int ks = 0; ks < 8; ++ks) {
        const int kk = ks * 8;
        uint32_t ah[2][4], al[2][4];
#pragma unroll
        for (int ma = 0; ma < 2; ++ma) {
            int r0 = wm * 32 + ma * 16 + g;
            ah[ma][0] = Ahi[r0 * SC_STRIDE + kk + t];
            ah[ma][1] = Ahi[(r0 + 8) * SC_STRIDE + kk + t];
            ah[ma][2] = Ahi[r0 * SC_STRIDE + kk + t + 4];
            ah[ma][3] = Ahi[(r0 + 8) * SC_STRIDE + kk + t + 4];
            al[ma][0] = Alo[r0 * SC_STRIDE + kk + t];
            al[ma][1] = Alo[(r0 + 8) * SC_STRIDE + kk + t];
            al[ma][2] = Alo[r0 * SC_STRIDE + kk + t + 4];
            al[ma][3] = Alo[(r0 + 8) * SC_STRIDE + kk + t + 4];
        }
#pragma unroll
        for (int nb = 0; nb < 8; ++nb) {
            int n0 = wn * 64 + nb * 8 + g;
            uint32_t bh0 = Bhi[n0 * SC_STRIDE + kk + t];
            uint32_t bh1 = Bhi[n0 * SC_STRIDE + kk + t + 4];
            uint32_t bl0 = Blo[n0 * SC_STRIDE + kk + t];
            uint32_t bl1 = Blo[n0 * SC_STRIDE + kk + t + 4];
#pragma unroll
            for (int ma = 0; ma < 2; ++ma) {
                mma_tf32(acc[ma][nb], ah[ma], bh0, bh1);
                mma_tf32(acc[ma][nb], ah[ma], bl0, bl1);
                mma_tf32(acc[ma][nb], al[ma], bh0, bh1);
            }
        }
    }

    const float scale = 0.015625f;  // 1/64
#pragma unroll
    for (int ma = 0; ma < 2; ++ma) {
        int row0 = bm * 128 + wm * 32 + ma * 16 + g;
#pragma unroll
        for (int nb = 0; nb < 8; ++nb) {
            int col = bx * 128 + wn * 64 + nb * 8 + 2 * t;
            float* p0 = g_P + ((size_t)b * S_ + row0) * S_ + col;
            float* p1 = g_P + ((size_t)b * S_ + row0 + 8) * S_ + col;
            *reinterpret_cast<float2*>(p0) =
                make_float2(acc[ma][nb][0] * scale, acc[ma][nb][1] * scale);
            *reinterpret_cast<float2*>(p1) =
                make_float2(acc[ma][nb][2] * scale, acc[ma][nb][3] * scale);
        }
    }
}

// ---------------- kernel 3: softmax + threefry dropout, fp32 -> fp16 --------
__global__ void __launch_bounds__(256) k_softmax_drop() {
    const size_t row = blockIdx.x;                 // b*2048 + i
    const float* p = g_P + row * (size_t)S_;
    __half2* ph = reinterpret_cast<__half2*>(g_Ph + row * (size_t)S_);
    const int tid  = threadIdx.x;
    const int lane = tid & 31;
    const int w    = tid >> 5;

    float2 v[4];
#pragma unroll
    for (int k = 0; k < 4; ++k)
        v[k] = *reinterpret_cast<const float2*>(p + 2 * tid + 512 * k);

    float mx = fmaxf(v[0].x, v[0].y);
#pragma unroll
    for (int k = 1; k < 4; ++k) mx = fmaxf(mx, fmaxf(v[k].x, v[k].y));
#pragma unroll
    for (int o = 16; o > 0; o >>= 1) mx = fmaxf(mx, __shfl_xor_sync(0xffffffffu, mx, o));

    __shared__ float redmax[8];
    __shared__ float redsum[8];
    if (lane == 0) redmax[w] = mx;
    __syncthreads();
    float M = redmax[0];
#pragma unroll
    for (int i = 1; i < 8; ++i) M = fmaxf(M, redmax[i]);

    float e[8];
    float s = 0.f;
#pragma unroll
    for (int k = 0; k < 4; ++k) {
        e[2 * k]     = __expf(v[k].x - M);
        e[2 * k + 1] = __expf(v[k].y - M);
        s += e[2 * k] + e[2 * k + 1];
    }
#pragma unroll
    for (int o = 16; o > 0; o >>= 1) s += __shfl_xor_sync(0xffffffffu, s, o);
    if (lane == 0) redsum[w] = s;
    __syncthreads();
    float Z = redsum[0];
#pragma unroll
    for (int i = 1; i < 8; ++i) Z += redsum[i];

    const float f = (1.0f / Z) * (1.0f / 0.75f);
    const size_t base = row * (size_t)S_;
#pragma unroll
    for (int k = 0; k < 4; ++k) {
        size_t idx = base + (size_t)(2 * tid + 512 * k);
        float f0 = jax_keep(idx)     ? e[2 * k] * f     : 0.0f;
        float f1 = jax_keep(idx + 1) ? e[2 * k + 1] * f : 0.0f;
        ph[tid + 256 * k] = __floats2half2_rn(f0, f1);
    }
}

// ---------------- kernel 4: PV via mma.sync fp16 -----------------------------
// out tile [128 x 128] = Ph[128 x 2048] @ qTh^T ; m16n8k16, BK=32, dbl-buffer.
#define PV_STRIDE 20                                // words (= 40 halfs) per row
#define PV_BUF_WORDS (128 * PV_STRIDE)              // 2560 words per tile buffer
#define PV_SMEM_TOTAL (4 * PV_BUF_WORDS * 4)        // A0,A1,B0,B1 = 40960 B

__global__ void __launch_bounds__(256, 2) k_pv_mma(float* __restrict__ out) {
    extern __shared__ uint32_t sm[];
    const int tid = threadIdx.x;
    const int wid = tid >> 5;
    const int lane = tid & 31;
    const int g = lane >> 2, t = lane & 3;
    const int wm = wid >> 1, wn = wid & 1;
    const int bn = blockIdx.x, bm = blockIdx.y, b = blockIdx.z;

    const __half* Ag = g_Ph + (size_t)b * S_ * S_ + (size_t)bm * 128 * S_;
    const __half* Bg = g_qTh + (size_t)bn * 128 * S_;

    float acc[2][8][4];
#pragma unroll
    for (int i = 0; i < 2; ++i)
#pragma unroll
        for (int j = 0; j < 8; ++j)
#pragma unroll
            for (int k = 0; k < 4; ++k) acc[i][j][k] = 0.f;

    auto stage = [&](int chunk, int buf) {
        const int k0 = chunk * 32;      // in halfs
        uint32_t* Asb = sm + buf * PV_BUF_WORDS;
        uint32_t* Bsb = sm + 2 * PV_BUF_WORDS + buf * PV_BUF_WORDS;
#pragma unroll
        for (int l = 0; l < 2; ++l) {
            int slot = tid + l * 256;    // 0..511
            int row  = slot >> 2;        // 0..127
            int c    = slot & 3;         // 16B chunk (8 halfs)
            uint4 va = *reinterpret_cast<const uint4*>(Ag + (size_t)row * S_ + k0 + c * 8);
            *reinterpret_cast<uint4*>(&Asb[row * PV_STRIDE + c * 4]) = va;
            uint4 vb = *reinterpret_cast<const uint4*>(Bg + (size_t)row * S_ + k0 + c * 8);
            *reinterpret_cast<uint4*>(&Bsb[row * PV_STRIDE + c * 4]) = vb;
        }
    };

    stage(0, 0);
    __syncthreads();

    for (int ch = 0; ch < S_ / 32; ++ch) {
        const int buf = ch & 1;
        if (ch + 1 < S_ / 32) stage(ch + 1, buf ^ 1);

        const uint32_t* Asb = sm + buf * PV_BUF_WORDS;
        const uint32_t* Bsb = sm + 2 * PV_BUF_WORDS + buf * PV_BUF_WORDS;

#pragma unroll
        for (int ks = 0; ks < 2; ++ks) {      // two k16 steps per BK=32
            const int kw = ks * 8;            // word offset (16 halfs)
            uint32_t af[2][4];
#pragma unroll
            for (int ma = 0; ma < 2; ++ma) {
                int r0 = wm * 32 + ma * 16 + g;
                af[ma][0] = Asb[r0 * PV_STRIDE + kw + t];
                af[ma][1] = Asb[(r0 + 8) * PV_STRIDE + kw + t];
                af[ma][2] = Asb[r0 * PV_STRIDE + kw + t + 4];
                af[ma][3] = Asb[(r0 + 8) * PV_STRIDE + kw + t + 4];
            }
#pragma unroll
            for (int nb = 0; nb < 8; ++nb) {
                int n0 = wn * 64 + nb * 8 + g;
                uint32_t b0 = Bsb[n0 * PV_STRIDE + kw + t];
                uint32_t b1 = Bsb[n0 * PV_STRIDE + kw + t + 4];
                mma_f16(acc[0][nb], af[0], b0, b1);
                mma_f16(acc[1][nb], af[1], b0, b1);
            }
        }
        __syncthreads();
    }

#pragma unroll
    for (int ma = 0; ma < 2; ++ma) {
        int row0 = bm * 128 + wm * 32 + ma * 16 + g;
#pragma unroll
        for (int nb = 0; nb < 8; ++nb) {
            int col = bn * 128 + wn * 64 + nb * 8 + 2 * t;
            float* p0 = out + ((size_t)b * S_ + row0) * DV_ + col;
            float* p1 = out + ((size_t)b * S_ + row0 + 8) * DV_ + col;
            *reinterpret_cast<float2*>(p0) = make_float2(acc[ma][nb][0], acc[ma][nb][1]);
            *reinterpret_cast<float2*>(p1) = make_float2(acc[ma][nb][2], acc[ma][nb][3]);
        }
    }
}

// ---------------- launch -----------------------------------------------------
extern "C" void kernel_launch(void* const* d_in, const int* in_sizes, int n_in,
                              void* d_out, int out_size) {
    const float* x1 = (const float*)d_in[0];   // [16,2048,64]
    const float* m  = (const float*)d_in[1];   // [64,512]
    const float* n  = (const float*)d_in[2];   // [2048,512]
    const float* q  = (const float*)d_in[3];   // [2048,512]
    float* out = (float*)d_out;                // [16,2048,512]

    cudaFuncSetAttribute(k_scores_mma, cudaFuncAttributeMaxDynamicSharedMemorySize,
                         SC_SMEM_TOTAL);
    cudaFuncSetAttribute(k_pv_mma, cudaFuncAttributeMaxDynamicSharedMemorySize,
                         PV_SMEM_TOTAL);

    k_build_K<<<S_, D_>>>(m, n);

    dim3 gt(DV_ / 32, S_ / 32);
    k_qT<<<gt, dim3(32, 8)>>>(q);

    dim3 g2(S_ / 128, S_ / 128, B_);
    k_scores_mma<<<g2, 256, SC_SMEM_TOTAL>>>(x1);

    k_softmax_drop<<<B_ * S_, 256>>>();

    dim3 g4(DV_ / 128, S_ / 128, B_);
    k_pv_mma<<<g4, 256, PV_SMEM_TOTAL>>>(out);
}